// round 14
// baseline (speedup 1.0000x reference)
#include <cuda_runtime.h>
#include <cuda_bf16.h>

#define NB 16384
#define DD 2048
#define BQ 64

#define BM 128
#define BN 64
#define BK 64
#define NCHUNK (DD / BK)
#define NSTAGE 4
#define PA 68   // fp32 A stage pitch (floats); 68 % 32 == 4
#define PB 72   // bf16 pitch (elems) for B stages and A bufs (R1/R6-proven)

#define STAGE_BYTES (BM * PA * 4 + BN * PB * 2)  // 34816 + 9216 = 44032
#define ABUF_BYTES (BM * PB * 2)                 // 18432
#define SMEM_BYTES (NSTAGE * STAGE_BYTES + 2 * ABUF_BYTES)  // 212992

__device__ float g_mat[BQ * NB];
__device__ __align__(16) __nv_bfloat16 g_fqB[BQ * DD];  // bf16(RN) copy of f
__device__ float g_qm[BQ * 4], g_qs[BQ * 4], g_qp[BQ * 4];
__device__ unsigned g_cnt = 0;

#define CP_ASYNC16(dst, src)                                                  \
    asm volatile("cp.async.cg.shared.global [%0], [%1], 16;\n" ::"r"(dst),    \
                 "l"(src))
#define CP_COMMIT asm volatile("cp.async.commit_group;\n")
#define CP_WAIT(N) asm volatile("cp.async.wait_group %0;\n" ::"n"(N))

#define LDSM4(r0, r1, r2, r3, addr)                                          \
    asm volatile("ldmatrix.sync.aligned.m8n8.x4.shared.b16 {%0,%1,%2,%3}, [%4];\n" \
                 : "=r"(r0), "=r"(r1), "=r"(r2), "=r"(r3)                    \
                 : "r"(addr))

#define MMA16816(d, a, b0, b1)                                               \
    asm volatile("mma.sync.aligned.m16n8k16.row.col.f32.bf16.bf16.f32 "      \
                 "{%0,%1,%2,%3}, {%4,%5,%6,%7}, {%8,%9}, {%0,%1,%2,%3};\n"   \
                 : "+f"(d[0]), "+f"(d[1]), "+f"(d[2]), "+f"(d[3])            \
                 : "r"(a[0]), "r"(a[1]), "r"(a[2]), "r"(a[3]), "r"(b0), "r"(b1))

__device__ __forceinline__ float wmax(float v) {
#pragma unroll
    for (int o = 16; o > 0; o >>= 1)
        v = fmaxf(v, __shfl_xor_sync(0xffffffffu, v, o));
    return v;
}
__device__ __forceinline__ float wmin(float v) {
#pragma unroll
    for (int o = 16; o > 0; o >>= 1)
        v = fminf(v, __shfl_xor_sync(0xffffffffu, v, o));
    return v;
}
__device__ __forceinline__ float wsum(float v) {
#pragma unroll
    for (int o = 16; o > 0; o >>= 1)
        v += __shfl_xor_sync(0xffffffffu, v, o);
    return v;
}

// ---------------------------------------------------------------------------
// K0: convert f -> bf16 (RN) once. Triggers PDL early so the gemm can launch
// and issue its (independent) A prefetches while this runs.
// ---------------------------------------------------------------------------
__global__ __launch_bounds__(256) void prep_kernel(const float* __restrict__ fq)
{
    int t = blockIdx.x * 256 + threadIdx.x;  // 128 blocks -> 32768 float4s
    float4 v = ((const float4*)fq)[t];
    __nv_bfloat162 p0 = __floats2bfloat162_rn(v.x, v.y);
    __nv_bfloat162 p1 = __floats2bfloat162_rn(v.z, v.w);
    uint2 u;
    u.x = *(unsigned*)&p0;
    u.y = *(unsigned*)&p1;
    ((uint2*)g_fqB)[t] = u;
    cudaTriggerProgrammaticLaunchCompletion();
}

// ---------------------------------------------------------------------------
// K1: R10-proven convert-ahead pipeline. PDL changes only the prologue:
// A-chunks 0..2 are prefetched BEFORE cudaGridDependencySynchronize() (they
// read feats, independent of prep); B loads (g_fqB) follow the sync as one
// extra commit group. Group->chunk mapping: 0..2 = A0..A2, 3 = B0..2,
// 4+k = chunk 3+k (A+B). In-loop wait(1) guarantees group c+2 = chunk c+1 --
// identical arithmetic to R10. Triggers after the mainloop so post can
// launch during the epilogue + CTA-spread tail.
// ---------------------------------------------------------------------------
__global__ __launch_bounds__(256) void gemm_copy_kernel(
    const float* __restrict__ feats,   // [16384, 2048]
    float* __restrict__ outF)          // d_out + 1 (misaligned for float4!)
{
    extern __shared__ __align__(16) char smem[];

    const int tid  = threadIdx.x;
    const int lane = tid & 31;
    const int warp = tid >> 5;
    const int wm = warp & 3;   // 4 warps along M (j)
    const int wn = warp >> 2;  // 2 warps along N (b)
    const int rowBase = blockIdx.x * BM;

    const int c4 = tid & 15;   // float4 col within 64-col chunk
    const int r0 = tid >> 4;   // base row (step 16)

    float acc[2][4][4];
#pragma unroll
    for (int i = 0; i < 2; i++)
#pragma unroll
        for (int j = 0; j < 4; j++)
#pragma unroll
            for (int k = 0; k < 4; k++) acc[i][j][k] = 0.f;

    auto stA  = [&](int s) { return (float*)(smem + s * STAGE_BYTES); };
    auto stB  = [&](int s) {
        return (__nv_bfloat16*)(smem + s * STAGE_BYTES + BM * PA * 4);
    };
    auto bufA = [&](int d) {
        return (__nv_bfloat16*)(smem + NSTAGE * STAGE_BYTES + d * ABUF_BYTES);
    };

    auto prefetchA = [&](int ck) {   // A only, own commit group
        const int s = ck & (NSTAGE - 1);
        float* A = stA(s);
        const float* src = feats + (size_t)rowBase * DD + ck * BK;
#pragma unroll
        for (int j = 0; j < 8; j++) {
            int r = r0 + 16 * j;
            unsigned d =
                (unsigned)__cvta_generic_to_shared(A + r * PA + c4 * 4);
            CP_ASYNC16(d, src + (size_t)r * DD + c4 * 4);
        }
        CP_COMMIT;
    };
    auto prefetchB = [&](int ck) {   // B only, NO commit (caller commits)
        const int s = ck & (NSTAGE - 1);
        __nv_bfloat16* B = stB(s);
        const __nv_bfloat16* bsrc = g_fqB + ck * BK;
        int row = tid >> 2;
        int p = tid & 3;
        unsigned d0 =
            (unsigned)__cvta_generic_to_shared(B + row * PB + p * 8);
        CP_ASYNC16(d0, bsrc + (size_t)row * DD + p * 8);
        unsigned d1 =
            (unsigned)__cvta_generic_to_shared(B + row * PB + (p + 4) * 8);
        CP_ASYNC16(d1, bsrc + (size_t)row * DD + (p + 4) * 8);
    };
    auto prefetch = [&](int ck) {    // combined A+B, one group (mainloop)
        const int s = ck & (NSTAGE - 1);
        float* A = stA(s);
        const float* src = feats + (size_t)rowBase * DD + ck * BK;
#pragma unroll
        for (int j = 0; j < 8; j++) {
            int r = r0 + 16 * j;
            unsigned d =
                (unsigned)__cvta_generic_to_shared(A + r * PA + c4 * 4);
            CP_ASYNC16(d, src + (size_t)r * DD + c4 * 4);
        }
        prefetchB(ck);
        CP_COMMIT;
    };

    // convert chunk ck: bf16 pack into Ab (float4 path) + DENSE copy to outF
    auto convert = [&](int ck) {
        const float* A = stA(ck & (NSTAGE - 1));
        __nv_bfloat16* Ab = bufA(ck & 1);
#pragma unroll
        for (int j = 0; j < 8; j++) {
            int r = r0 + 16 * j;
            float4 v = *(const float4*)(A + r * PA + c4 * 4);
            __nv_bfloat162 h0 = __floats2bfloat162_rn(v.x, v.y);
            __nv_bfloat162 h1 = __floats2bfloat162_rn(v.z, v.w);
            uint2 u;
            u.x = *(unsigned*)&h0;
            u.y = *(unsigned*)&h1;
            *(uint2*)(Ab + r * PB + c4 * 4) = u;
        }
        // dense copy: lanes contiguous -> 1 wavefront per STG.32
        float* orow = outF + (size_t)rowBase * DD + ck * BK;
#pragma unroll
        for (int j = 0; j < 16; j++) {
            int r = warp + 8 * j;
            __stcs(orow + (size_t)r * DD + lane,      A[r * PA + lane]);
            __stcs(orow + (size_t)r * DD + 32 + lane, A[r * PA + 32 + lane]);
        }
    };

    const int matid = lane >> 3, mr = lane & 7;

    // prologue: A prefetches overlap the still-running prep kernel
    prefetchA(0);                         // group 0
    prefetchA(1);                         // group 1
    prefetchA(2);                         // group 2
    cudaGridDependencySynchronize();      // prep's g_fqB now visible
    prefetchB(0);
    prefetchB(1);
    prefetchB(2);
    CP_COMMIT;                            // group 3 (B chunks 0..2)
    CP_WAIT(0);                           // A0..2 + B0..2 complete
    __syncthreads();
    convert(0);

#pragma unroll 1
    for (int c = 0; c < NCHUNK; c++) {
        // need chunk c+1 complete before the barrier (for convert(c+1));
        // committed = 4 + c groups -> wait(1) completes through group c+2
        // = chunk c+1 (and B0..2 in group 3).
        if (c + 1 < NCHUNK) {
            if (c + 2 <= NCHUNK - 1) CP_WAIT(1);
            else                     CP_WAIT(0);
        }
        __syncthreads();
        if (c + 3 < NCHUNK) prefetch(c + 3);
        if (c + 1 < NCHUNK) convert(c + 1);

        // mma chunk c from Ab[c&1] (written last iteration, pre-barrier)
        const __nv_bfloat16* Ab = bufA(c & 1);
        const __nv_bfloat16* Bs = stB(c & (NSTAGE - 1));
#pragma unroll
        for (int ks = 0; ks < 4; ks++) {
            unsigned af[2][4], bf2[2][4];
#pragma unroll
            for (int mi = 0; mi < 2; mi++) {
                const __nv_bfloat16* p =
                    Ab + (wm * 32 + mi * 16 + (matid & 1) * 8 + mr) * PB +
                    ks * 16 + (matid >> 1) * 8;
                unsigned ad = (unsigned)__cvta_generic_to_shared(p);
                LDSM4(af[mi][0], af[mi][1], af[mi][2], af[mi][3], ad);
            }
#pragma unroll
            for (int gi = 0; gi < 2; gi++) {
                const __nv_bfloat16* p =
                    Bs + (wn * 32 + gi * 16 + (matid >> 1) * 8 + mr) * PB +
                    ks * 16 + (matid & 1) * 8;
                unsigned ad = (unsigned)__cvta_generic_to_shared(p);
                LDSM4(bf2[gi][0], bf2[gi][1], bf2[gi][2], bf2[gi][3], ad);
            }
#pragma unroll
            for (int mi = 0; mi < 2; mi++)
#pragma unroll
                for (int nt = 0; nt < 4; nt++)
                    MMA16816(acc[mi][nt], af[mi],
                             bf2[nt >> 1][(nt & 1) * 2],
                             bf2[nt >> 1][(nt & 1) * 2 + 1]);
        }
    }

    // mainloop done -> let post launch (its sync still waits for our writes)
    cudaTriggerProgrammaticLaunchCompletion();

    // epilogue: accums -> smem transpose -> g_mat[b][j]
    __syncthreads();
    float* sC = (float*)smem;  // [128][65]
    const int g = lane >> 2, t4 = lane & 3;
#pragma unroll
    for (int mi = 0; mi < 2; mi++)
#pragma unroll
        for (int nt = 0; nt < 4; nt++) {
            int ml = wm * 32 + mi * 16 + g;
            int nn = wn * 32 + nt * 8 + t4 * 2;
            sC[ml * 65 + nn]           = acc[mi][nt][0];
            sC[ml * 65 + nn + 1]       = acc[mi][nt][1];
            sC[(ml + 8) * 65 + nn]     = acc[mi][nt][2];
            sC[(ml + 8) * 65 + nn + 1] = acc[mi][nt][3];
        }
    __syncthreads();
#pragma unroll 1
    for (int i = 0; i < 32; i++) {
        int e = i * 256 + tid;
        int bb = e >> 7, j = e & 127;
        g_mat[bb * NB + rowBase + j] = sC[j * 65 + bb];
    }
}

// ---------------------------------------------------------------------------
// K2: PDL-overlapped post. Pre-sync: all loads that don't depend on the gemm
// (labels, indexes, feats, fweak, momentum reduction). Sync gates g_mat
// reads and out+1 writes (the momentum overwrite must follow gemm's copy).
// Blocks 0..255: loss quarters + last-block combine. 256..319: momentum.
// ---------------------------------------------------------------------------
__global__ __launch_bounds__(256) void post_kernel(
    const int* __restrict__ labels, const int* __restrict__ indexes,
    const float* __restrict__ feats, const float* __restrict__ fweak,
    float* __restrict__ out)
{
    __shared__ float sA[8], sB[8], sD[8];
    __shared__ float sQ[64];
    __shared__ int s_last;
    const int bx = blockIdx.x;
    const int tid = threadIdx.x;
    const int lane = tid & 31;
    const int wid = tid >> 5;

    if (bx >= 256) {
        // ---- momentum update (last duplicate index wins) ----
        const int b = bx - 256;
        const int idx = indexes[b];
        for (int b2 = b + 1; b2 < BQ; b2++)
            if (indexes[b2] == idx) return;   // never syncs, never writes: ok

        float w[8];
        float ssum = 0.f;
        const float* fr = feats + (size_t)idx * DD;
        const float* wr = fweak + (size_t)b * DD;
#pragma unroll
        for (int i = 0; i < 8; i++) {
            int k = i * 256 + tid;
            float v = fr[k] * 0.2f + wr[k] * 0.8f;
            w[i] = v;
            ssum += v * v;
        }
        ssum = wsum(ssum);
        if (lane == 0) sA[wid] = ssum;
        __syncthreads();
        float tot = sA[0];
#pragma unroll
        for (int k = 1; k < 8; k++) tot += sA[k];
        float inv = 1.0f / fmaxf(sqrtf(tot), 1e-12f);
        cudaGridDependencySynchronize();   // gemm's copy of row idx is done
        float* orow = out + 1 + (size_t)idx * DD;
#pragma unroll
        for (int i = 0; i < 8; i++) orow[i * 256 + tid] = w[i] * inv;
        return;
    }

    // ---- loss quarter ----
    const int b = bx >> 2, q = bx & 3;
    const int blab = labels[indexes[b]];
    const float it = 1.0f / 0.07f;

    const float4* row4 = (const float4*)(g_mat + b * NB) + q * 1024;
    const int4*   lab4 = (const int4*)labels + q * 1024;

    int4 l4r[4];
#pragma unroll
    for (int k = 0; k < 4; k++) l4r[k] = lab4[tid + k * 256];

    cudaGridDependencySynchronize();   // g_mat now visible

    float v[16];
    int   neg[16];
    float mneg = -INFINITY, pmin = INFINITY;
#pragma unroll
    for (int k = 0; k < 4; k++) {
        float4 v4 = row4[tid + k * 256];
        v[k * 4 + 0] = v4.x * it; neg[k * 4 + 0] = (l4r[k].x != blab);
        v[k * 4 + 1] = v4.y * it; neg[k * 4 + 1] = (l4r[k].y != blab);
        v[k * 4 + 2] = v4.z * it; neg[k * 4 + 2] = (l4r[k].z != blab);
        v[k * 4 + 3] = v4.w * it; neg[k * 4 + 3] = (l4r[k].w != blab);
    }
#pragma unroll
    for (int k = 0; k < 16; k++) {
        if (neg[k]) mneg = fmaxf(mneg, v[k]);
        else        pmin = fminf(pmin, v[k]);
    }
    float tmax = mneg;
    float wm_ = wmax(mneg);
    float wp_ = wmin(pmin);
    if (lane == 0) { sA[wid] = wm_; sB[wid] = wp_; }
    __syncthreads();
    float M = sA[0], P = sB[0];
#pragma unroll
    for (int k = 1; k < 8; k++) {
        M = fmaxf(M, sA[k]);
        P = fminf(P, sB[k]);
    }
    const float thr = M - 25.0f;  // exp(-25)~1.4e-11: exact vs top-K lse

    float s = 0.f;
    if (tmax > thr) {
#pragma unroll
        for (int k = 0; k < 16; k++)
            if (neg[k] && v[k] > thr) s += __expf(v[k] - M);
    }
    s = wsum(s);
    if (lane == 0) sD[wid] = s;
    __syncthreads();
    if (tid == 0) {
        float S = sD[0];
#pragma unroll
        for (int k = 1; k < 8; k++) S += sD[k];
        g_qm[bx] = M;
        g_qs[bx] = S;
        g_qp[bx] = P;
        __threadfence();
        unsigned c = atomicAdd(&g_cnt, 1u);
        s_last = (c == 4 * BQ - 1);
    }
    __syncthreads();

    if (s_last) {
        float rl = 0.f;
        if (tid < BQ) {
            float m = -INFINITY, p = INFINITY;
#pragma unroll
            for (int qq = 0; qq < 4; qq++) {
                m = fmaxf(m, *((volatile float*)&g_qm[tid * 4 + qq]));
                p = fminf(p, *((volatile float*)&g_qp[tid * 4 + qq]));
            }
            float ss = 0.f;
#pragma unroll
            for (int qq = 0; qq < 4; qq++) {
                float mq = *((volatile float*)&g_qm[tid * 4 + qq]);
                if (mq > -INFINITY)
                    ss += *((volatile float*)&g_qs[tid * 4 + qq]) *
                          __expf(mq - m);
            }
            float nm = fmaxf(m, p);
            float ns = ss * __expf(m - nm) + __expf(p - nm);
            rl = nm + logf(ns) - p;  // lse - logit0
        }
        if (tid < BQ) sQ[tid] = rl;
        __syncthreads();
        if (tid < 32) {
            float acc2 = sQ[tid] + sQ[tid + 32];
            acc2 = wsum(acc2);
            if (tid == 0) {
                out[0] = acc2 * (1.0f / 64.0f);
                g_cnt = 0;  // reset for next graph replay
            }
        }
    }
}

// ---------------------------------------------------------------------------
extern "C" void kernel_launch(void* const* d_in, const int* in_sizes, int n_in,
                              void* d_out, int out_size)
{
    const float* fq      = (const float*)d_in[0];  // f        [64,2048]
    const float* fweak   = (const float*)d_in[1];  // f_weak   [64,2048]
    const int*   indexes = (const int*)d_in[2];    // [64]
    const float* feats   = (const float*)d_in[3];  // features [16384,2048]
    const int*   labels  = (const int*)d_in[4];    // [16384]
    float* out = (float*)d_out;                    // [0]=loss, [1:]=features

    cudaFuncSetAttribute(gemm_copy_kernel,
                         cudaFuncAttributeMaxDynamicSharedMemorySize,
                         SMEM_BYTES);

    prep_kernel<<<BQ * DD / (256 * 4), 256>>>(fq);

    cudaLaunchAttribute pdl[1];
    pdl[0].id = cudaLaunchAttributeProgrammaticStreamSerialization;
    pdl[0].val.programmaticStreamSerializationAllowed = 1;

    cudaLaunchConfig_t cfgG = {};
    cfgG.gridDim = dim3(NB / BM);
    cfgG.blockDim = dim3(256);
    cfgG.dynamicSmemBytes = SMEM_BYTES;
    cfgG.stream = 0;
    cfgG.attrs = pdl;
    cfgG.numAttrs = 1;
    cudaLaunchKernelEx(&cfgG, gemm_copy_kernel, feats, out + 1);

    cudaLaunchConfig_t cfgP = {};
    cfgP.gridDim = dim3(BQ * 4 + BQ);
    cfgP.blockDim = dim3(256);
    cfgP.dynamicSmemBytes = 0;
    cfgP.stream = 0;
    cfgP.attrs = pdl;
    cfgP.numAttrs = 1;
    cudaLaunchKernelEx(&cfgP, post_kernel, labels, indexes, feats, fweak, out);
}